// round 15
// baseline (speedup 1.0000x reference)
#include <cuda_runtime.h>
#include <cuda_fp16.h>
#include <cstdint>

// ---------------------------------------------------------------------------
// Problem shape
// ---------------------------------------------------------------------------
#define B_  16
#define N_  1024
#define D_  768
#define H_  12
#define HS_ 64
#define M_  (B_*N_)     // 16384 token rows
#define L_  2
#define EPS_ 1e-6f

// ---------------------------------------------------------------------------
// Scratch
// ---------------------------------------------------------------------------
__device__ __half g_xn [M_*D_];        // LN1(x)           (GEMM1 A)
__device__ __half g_wvT[D_*D_];        // Wv^T [n=h*64+k][d]
__device__ __half g_wfT[L_*D_*D_];     // Wf^T [l][n][d]
__device__ __half g_vc [H_*N_*N_];     // v [h][b*64+k][j] (circ B)
__device__ __half g_cc [H_*N_*N_];     // C [h][i][j]      (circ A)
__device__ __half g_x1h[M_*D_];        // x + y residual (fp16 only)
__device__ __half g_th [M_*D_];        // ffn gemm out (fp16)
__device__ __half g_zh [M_*D_];        // swish(ln(t))     (FFN2 A)

// ---------------------------------------------------------------------------
// Helpers
// ---------------------------------------------------------------------------
__device__ __forceinline__ uint32_t smem_u32(const void* p) {
    uint32_t a;
    asm("{ .reg .u64 t; cvta.to.shared.u64 t, %1; cvt.u32.u64 %0, t; }"
        : "=r"(a) : "l"(p));
    return a;
}
__device__ __forceinline__ void ldsm_x4(uint32_t* d, uint32_t addr) {
    asm volatile("ldmatrix.sync.aligned.m8n8.x4.shared.b16 {%0,%1,%2,%3}, [%4];"
                 : "=r"(d[0]), "=r"(d[1]), "=r"(d[2]), "=r"(d[3]) : "r"(addr));
}
__device__ __forceinline__ void mma16816(float* d, const uint32_t* a,
                                         uint32_t b0, uint32_t b1) {
    asm volatile(
        "mma.sync.aligned.m16n8k16.row.col.f32.f16.f16.f32 "
        "{%0,%1,%2,%3}, {%4,%5,%6,%7}, {%8,%9}, {%0,%1,%2,%3};"
        : "+f"(d[0]), "+f"(d[1]), "+f"(d[2]), "+f"(d[3])
        : "r"(a[0]), "r"(a[1]), "r"(a[2]), "r"(a[3]), "r"(b0), "r"(b1));
}
#define CP_ASYNC(dst, src) \
    asm volatile("cp.async.cg.shared.global [%0], [%1], 16;" :: "r"(dst), "l"(src))
#define CP_COMMIT() asm volatile("cp.async.commit_group;" ::: "memory")
#define CP_WAIT(n)  asm volatile("cp.async.wait_group %0;" :: "n"(n) : "memory")

// ---------------------------------------------------------------------------
// Weight prep: tiled transposes (both sides coalesced)
// ---------------------------------------------------------------------------
__global__ void __launch_bounds__(256) conv_wvT_kernel(const float* __restrict__ Wv) {
    __shared__ float ts[32][33];
    int d0 = blockIdx.x * 32, k0 = blockIdx.y * 32, h = blockIdx.z;
    int tx = threadIdx.x & 31, ty = threadIdx.x >> 5;
    #pragma unroll
    for (int r = 0; r < 4; r++) {
        int d = d0 + ty + r * 8;
        ts[ty + r * 8][tx] = Wv[((size_t)h * D_ + d) * HS_ + k0 + tx];
    }
    __syncthreads();
    #pragma unroll
    for (int r = 0; r < 4; r++) {
        int k = k0 + ty + r * 8;
        g_wvT[(size_t)(h * HS_ + k) * D_ + d0 + tx] = __float2half(ts[tx][ty + r * 8]);
    }
}
__global__ void __launch_bounds__(256) conv_wfT_kernel(const float* __restrict__ Wf) {
    __shared__ float ts[32][33];
    int d0 = blockIdx.x * 32, n0 = blockIdx.y * 32, l = blockIdx.z;
    int tx = threadIdx.x & 31, ty = threadIdx.x >> 5;
    #pragma unroll
    for (int r = 0; r < 4; r++) {
        int d = d0 + ty + r * 8;
        ts[ty + r * 8][tx] = Wf[((size_t)l * D_ + d) * D_ + n0 + tx];
    }
    __syncthreads();
    #pragma unroll
    for (int r = 0; r < 4; r++) {
        int n = n0 + ty + r * 8;
        g_wfT[((size_t)l * D_ + n) * D_ + d0 + tx] = __float2half(ts[tx][ty + r * 8]);
    }
}
__global__ void build_circ_kernel(const float* __restrict__ alpha) {
    int bid = blockIdx.x;           // h*1024 + i
    int h = bid >> 10, i = bid & 1023;
    const float* a = alpha + (size_t)h * N_;
    size_t base = (size_t)bid * N_;
    #pragma unroll
    for (int t = 0; t < 4; t++) {
        int j = threadIdx.x + t * 256;
        g_cc[base + j] = __float2half(a[(i - j) & (N_ - 1)]);
    }
}

// ---------------------------------------------------------------------------
// Warp-per-row LayerNorm (no smem, shuffle reduction). 8 rows/block.
// ---------------------------------------------------------------------------
__device__ __forceinline__ void warp_stats(const float4* v, float& mu, float& inv) {
    float s = 0.f, q = 0.f;
    #pragma unroll
    for (int i = 0; i < 6; i++) {
        s += v[i].x + v[i].y + v[i].z + v[i].w;
        q += v[i].x*v[i].x + v[i].y*v[i].y + v[i].z*v[i].z + v[i].w*v[i].w;
    }
    #pragma unroll
    for (int o = 16; o; o >>= 1) {
        s += __shfl_xor_sync(0xffffffffu, s, o);
        q += __shfl_xor_sync(0xffffffffu, q, o);
    }
    mu = s * (1.f / D_);
    float var = q * (1.f / D_) - mu * mu;
    inv = rsqrtf(var + EPS_);
}

__global__ void __launch_bounds__(256) ln1_kernel(
    const float* __restrict__ in, const float* __restrict__ scale,
    const float* __restrict__ bias)
{
    int warp = threadIdx.x >> 5, lane = threadIdx.x & 31;
    size_t row = (size_t)blockIdx.x * 8 + warp;
    const float4* p = reinterpret_cast<const float4*>(in + row * D_);
    const float4* sc = reinterpret_cast<const float4*>(scale);
    const float4* bi = reinterpret_cast<const float4*>(bias);
    float4 v[6];
    #pragma unroll
    for (int i = 0; i < 6; i++) v[i] = p[lane + 32 * i];
    float mu, inv;
    warp_stats(v, mu, inv);
    #pragma unroll
    for (int i = 0; i < 6; i++) {
        int g4 = lane + 32 * i;
        float4 s4 = sc[g4], b4 = bi[g4];
        __half2 h0 = __floats2half2_rn((v[i].x - mu) * inv * s4.x + b4.x,
                                       (v[i].y - mu) * inv * s4.y + b4.y);
        __half2 h1 = __floats2half2_rn((v[i].z - mu) * inv * s4.z + b4.z,
                                       (v[i].w - mu) * inv * s4.w + b4.w);
        uint2 u; u.x = *(uint32_t*)&h0; u.y = *(uint32_t*)&h1;
        *reinterpret_cast<uint2*>(g_xn + row * D_ + g4 * 4) = u;
    }
}

// input t is fp16. LAST=0: z = swish(LN(t)) -> g_zh
//                  LAST=1: out = log_cosh(swish(LN(t)) + x1h)
template<int LAST>
__global__ void __launch_bounds__(256) ln_swish_kernel(
    const float* __restrict__ scale, const float* __restrict__ bias,
    float* __restrict__ out, int rowOff)
{
    int warp = threadIdx.x >> 5, lane = threadIdx.x & 31;
    size_t row = (size_t)rowOff + blockIdx.x * 8 + warp;
    const uint2* p = reinterpret_cast<const uint2*>(g_th + row * D_);
    const float4* sc = reinterpret_cast<const float4*>(scale);
    const float4* bi = reinterpret_cast<const float4*>(bias);
    float4 v[6];
    #pragma unroll
    for (int i = 0; i < 6; i++) {
        uint2 u = p[lane + 32 * i];
        __half2 h0 = *(__half2*)&u.x, h1 = *(__half2*)&u.y;
        float2 f0 = __half22float2(h0), f1 = __half22float2(h1);
        v[i] = make_float4(f0.x, f0.y, f1.x, f1.y);
    }
    float mu, inv;
    warp_stats(v, mu, inv);
    #pragma unroll
    for (int i = 0; i < 6; i++) {
        int g4 = lane + 32 * i;
        float4 s4 = sc[g4], b4 = bi[g4];
        float r[4] = {(v[i].x - mu) * inv * s4.x + b4.x,
                      (v[i].y - mu) * inv * s4.y + b4.y,
                      (v[i].z - mu) * inv * s4.z + b4.z,
                      (v[i].w - mu) * inv * s4.w + b4.w};
        #pragma unroll
        for (int c = 0; c < 4; c++) r[c] = r[c] * (1.f / (1.f + expf(-r[c])));
        if (LAST) {
            uint2 ux = *reinterpret_cast<const uint2*>(g_x1h + row * D_ + g4 * 4);
            float2 xa = __half22float2(*(__half2*)&ux.x);
            float2 xb = __half22float2(*(__half2*)&ux.y);
            float xs[4] = {xa.x, xa.y, xb.x, xb.y};
            float4 o4;
            float* po = &o4.x;
            #pragma unroll
            for (int c = 0; c < 4; c++) {
                float sum = r[c] + xs[c];
                float ax = fabsf(sum);
                po[c] = ax + log1pf(expf(-2.f * ax)) - 0.69314718055994530942f;
            }
            *reinterpret_cast<float4*>(out + row * D_ + g4 * 4) = o4;
        } else {
            __half2 h0 = __floats2half2_rn(r[0], r[1]);
            __half2 h1 = __floats2half2_rn(r[2], r[3]);
            uint2 u; u.x = *(uint32_t*)&h0; u.y = *(uint32_t*)&h1;
            *reinterpret_cast<uint2*>(g_zh + row * D_ + g4 * 4) = u;
        }
    }
}

// ---------------------------------------------------------------------------
// HMMA fp16 GEMM (fp32 accum). Block 128x128, BK=32, 3-stage cp.async,
// 2 CTAs/SM. 8 warps (2m x 4n), warp tile 64x32, m16n8k16.
// MODE 0: GEMM1 -> smem transpose, scatter v [h][b*64+k][j]; tileOff = col-tile
// MODE 1: circ  -> x1h = fp16(x + D); tileOff = head offset; strZ per head
// MODE 2: FFN   -> t = D + bias (fp16); rowOff = block-row offset
// ---------------------------------------------------------------------------
#define BM 128
#define BN 128
#define TILE_B   8192u            // 128x32 fp16
#define STAGE_B  (2u*TILE_B)      // A, B
#define NSTAGE   3
#define SMEM_BYTES (NSTAGE*STAGE_B)   // 49152 ; epi buffer 33280 fits

// 64B-row swizzle: 4 chunks of 16B; chunk' = cc ^ ((row>>1)&3)
__device__ __forceinline__ uint32_t sw_off(int row, int cc) {
    return (uint32_t)(row * 64 + ((cc ^ ((row >> 1) & 3)) << 4));
}

__device__ __forceinline__ void cp_tile(uint32_t dstBase, const __half* src,
                                        int rowBase, int kBase, int ld, int tid)
{
    const char* g = (const char*)src + ((size_t)rowBase * ld + kBase) * 2;
    #pragma unroll
    for (int t = 0; t < 2; t++) {
        int ci = tid + t * 256;
        int row = ci >> 2, cc = ci & 3;
        CP_ASYNC(dstBase + sw_off(row, cc), g + (size_t)row * ld * 2 + cc * 16);
    }
}

template<int MODE>
__global__ void __launch_bounds__(256, 2) tc_gemm(
    const __half* __restrict__ A, const __half* __restrict__ Bm,
    int Kdim, size_t strZ,
    const float* __restrict__ xin,            // mode1
    __half* __restrict__ out_h,               // mode0: vc, mode1: x1h, mode2: t
    const float* __restrict__ bias,           // mode2
    int tileOff, int rowOff)                  // col-tile / head ; block-row
{
    extern __shared__ char smem[];
    const int tid = threadIdx.x;
    const int wid = tid >> 5, lane = tid & 31;
    const uint32_t sbase = smem_u32(smem);

    const int mBase = (blockIdx.y + rowOff) * BM;
    const int nBase = (blockIdx.x + (MODE == 0 ? tileOff : 0)) * BN;
    const int bz = blockIdx.z;
    const __half* Ab = A  + (size_t)bz * strZ;
    const __half* Bb = Bm + (size_t)bz * strZ;

    const int warpM = wid >> 2;     // 0..1 (x64 rows)
    const int warpN = wid & 3;      // 0..3 (x32 cols)

    const int nc = Kdim >> 5;       // BK = 32

    #pragma unroll
    for (int s = 0; s < NSTAGE - 1; s++) {
        uint32_t sb = sbase + s * STAGE_B;
        cp_tile(sb,          Ab, mBase, s * 32, Kdim, tid);
        cp_tile(sb + TILE_B, Bb, nBase, s * 32, Kdim, tid);
        CP_COMMIT();
    }

    float acc[4][4][4] = {};
    const int lrow = lane & 15;
    const int lsel = lane >> 4;

    for (int c = 0; c < nc; c++) {
        CP_WAIT(NSTAGE - 2);
        __syncthreads();

        int pre = c + NSTAGE - 1;
        if (pre < nc) {
            uint32_t sb = sbase + (pre % NSTAGE) * STAGE_B;
            cp_tile(sb,          Ab, mBase, pre * 32, Kdim, tid);
            cp_tile(sb + TILE_B, Bb, nBase, pre * 32, Kdim, tid);
            CP_COMMIT();
        }

        uint32_t stA = sbase + (c % NSTAGE) * STAGE_B;
        uint32_t stB = stA + TILE_B;

        #pragma unroll
        for (int kk = 0; kk < 2; kk++) {
            int cc = kk * 2 + lsel;
            uint32_t aF[4][4], bF[2][4];
            #pragma unroll
            for (int mt = 0; mt < 4; mt++) {
                int r = warpM * 64 + mt * 16 + lrow;
                ldsm_x4(aF[mt], stA + sw_off(r, cc));
            }
            #pragma unroll
            for (int nt2 = 0; nt2 < 2; nt2++) {
                int r = warpN * 32 + nt2 * 16 + lrow;
                ldsm_x4(bF[nt2], stB + sw_off(r, cc));
            }
            #pragma unroll
            for (int mt = 0; mt < 4; mt++)
                #pragma unroll
                for (int nt = 0; nt < 4; nt++) {
                    uint32_t b0 = bF[nt >> 1][nt & 1];
                    uint32_t b1 = bF[nt >> 1][(nt & 1) + 2];
                    mma16816(acc[mt][nt], aF[mt], b0, b1);
                }
        }
    }
    CP_WAIT(0);

    const int mBaseW = mBase + warpM * 64;
    const int nBaseW = nBase + warpN * 32;

    if (MODE == 0) {
        // two 64-col chunks through smem [128][65], then column writes
        float* sbuf = reinterpret_cast<float*>(smem);
        const int LDS = 65;
        #pragma unroll
        for (int hf = 0; hf < 2; hf++) {
            __syncthreads();
            if ((warpN >> 1) == hf) {
                #pragma unroll
                for (int mt = 0; mt < 4; mt++)
                    #pragma unroll
                    for (int nt = 0; nt < 4; nt++) {
                        int rl = warpM * 64 + mt * 16 + (lane >> 2);
                        int cl = (warpN & 1) * 32 + nt * 8 + ((lane & 3) << 1);
                        sbuf[rl * LDS + cl]           = acc[mt][nt][0];
                        sbuf[rl * LDS + cl + 1]       = acc[mt][nt][1];
                        sbuf[(rl + 8) * LDS + cl]     = acc[mt][nt][2];
                        sbuf[(rl + 8) * LDS + cl + 1] = acc[mt][nt][3];
                    }
            }
            __syncthreads();
            #pragma unroll
            for (int i = 0; i < 8; i++) {
                int cl = wid * 8 + i;
                int cg = nBase + hf * 64 + cl;
                int h = cg >> 6, k = cg & 63;
                #pragma unroll
                for (int q = 0; q < 2; q++) {
                    int m = q * 64 + lane * 2;
                    int mg = mBase + m;
                    int b = mg >> 10, j = mg & 1023;
                    size_t o = (((size_t)(h << 10) + (b << 6) + k) << 10) + j;
                    __half2 hv = __floats2half2_rn(sbuf[m * LDS + cl],
                                                   sbuf[(m + 1) * LDS + cl]);
                    *reinterpret_cast<__half2*>(out_h + o) = hv;
                }
            }
        }
    } else {
        #pragma unroll
        for (int mt = 0; mt < 4; mt++)
            #pragma unroll
            for (int nt = 0; nt < 4; nt++) {
                int i0 = mBaseW + mt * 16 + (lane >> 2);
                int cl = nBaseW + nt * 8 + ((lane & 3) << 1);
                #pragma unroll
                for (int h2 = 0; h2 < 2; h2++) {
                    int i = i0 + h2 * 8;
                    float v0 = acc[mt][nt][h2 * 2];
                    float v1 = acc[mt][nt][h2 * 2 + 1];
                    if (MODE == 1) {
                        int b = cl >> 6, k = cl & 63;
                        size_t o = ((size_t)(b << 10) + i) * D_
                                   + (tileOff + bz) * HS_ + k;
                        *reinterpret_cast<__half2*>(out_h + o) =
                            __floats2half2_rn(xin[o] + v0, xin[o + 1] + v1);
                    } else {
                        size_t o = (size_t)i * D_ + cl;
                        *reinterpret_cast<__half2*>(out_h + o) =
                            __floats2half2_rn(v0 + bias[cl], v1 + bias[cl + 1]);
                    }
                }
            }
    }
}

// ---------------------------------------------------------------------------
// Launch: GEMMs strictly serial on main stream; LNs overlapped on s2.
// ---------------------------------------------------------------------------
extern "C" void kernel_launch(void* const* d_in, const int* in_sizes, int n_in,
                              void* d_out, int out_size)
{
    const float* x     = (const float*)d_in[0];
    const float* ln1_s = (const float*)d_in[1];
    const float* ln1_b = (const float*)d_in[2];
    const float* Wv    = (const float*)d_in[3];
    const float* alpha = (const float*)d_in[4];
    const float* Wf    = (const float*)d_in[5];
    const float* bf    = (const float*)d_in[6];
    const float* lnf_s = (const float*)d_in[7];
    const float* lnf_b = (const float*)d_in[8];
    float* out = (float*)d_out;

    static cudaStream_t s2 = nullptr, s3 = nullptr;
    static cudaEvent_t ev0, evWv, evWf, evC, evG[3];
    static cudaEvent_t evF1[2], evL0[2], evF2[2], evDone;
    if (!s2) {
        cudaStreamCreateWithFlags(&s2, cudaStreamNonBlocking);
        cudaStreamCreateWithFlags(&s3, cudaStreamNonBlocking);
        cudaEventCreateWithFlags(&ev0,  cudaEventDisableTiming);
        cudaEventCreateWithFlags(&evWv, cudaEventDisableTiming);
        cudaEventCreateWithFlags(&evWf, cudaEventDisableTiming);
        cudaEventCreateWithFlags(&evC,  cudaEventDisableTiming);
        for (int i = 0; i < 3; i++)
            cudaEventCreateWithFlags(&evG[i], cudaEventDisableTiming);
        for (int i = 0; i < 2; i++) {
            cudaEventCreateWithFlags(&evF1[i], cudaEventDisableTiming);
            cudaEventCreateWithFlags(&evL0[i], cudaEventDisableTiming);
            cudaEventCreateWithFlags(&evF2[i], cudaEventDisableTiming);
        }
        cudaEventCreateWithFlags(&evDone, cudaEventDisableTiming);
        cudaFuncSetAttribute(tc_gemm<0>, cudaFuncAttributeMaxDynamicSharedMemorySize, SMEM_BYTES);
        cudaFuncSetAttribute(tc_gemm<1>, cudaFuncAttributeMaxDynamicSharedMemorySize, SMEM_BYTES);
        cudaFuncSetAttribute(tc_gemm<2>, cudaFuncAttributeMaxDynamicSharedMemorySize, SMEM_BYTES);
    }

    __half *xn, *wvT, *wfT, *vc, *cc, *x1h, *th, *zh;
    cudaGetSymbolAddress((void**)&xn, g_xn);
    cudaGetSymbolAddress((void**)&wvT, g_wvT);
    cudaGetSymbolAddress((void**)&wfT, g_wfT);
    cudaGetSymbolAddress((void**)&vc, g_vc);
    cudaGetSymbolAddress((void**)&cc, g_cc);
    cudaGetSymbolAddress((void**)&x1h, g_x1h);
    cudaGetSymbolAddress((void**)&th, g_th);
    cudaGetSymbolAddress((void**)&zh, g_zh);

    // fork prep
    cudaEventRecord(ev0, 0);
    cudaStreamWaitEvent(s2, ev0, 0);
    cudaStreamWaitEvent(s3, ev0, 0);
    conv_wvT_kernel<<<dim3(D_/32, HS_/32, H_), 256, 0, s2>>>(Wv);
    cudaEventRecord(evWv, s2);
    build_circ_kernel<<<H_*N_, 256, 0, s2>>>(alpha);
    conv_wfT_kernel<<<dim3(D_/32, D_/32, L_), 256, 0, s3>>>(Wf);
    cudaEventRecord(evWf, s3);

    // main: LN1
    ln1_kernel<<<M_/8, 256>>>(x, ln1_s, ln1_b);
    cudaStreamWaitEvent(0, evWv, 0);

    // GEMM1 column chunks (4 heads each) pipelined with circ chunks on s2
    for (int c = 0; c < 3; c++) {
        tc_gemm<0><<<dim3(2, M_/BM, 1), 256, SMEM_BYTES>>>(
            xn, wvT, D_, 0, nullptr, vc, nullptr, 2 * c, 0);
        cudaEventRecord(evG[c], 0);
        cudaStreamWaitEvent(s2, evG[c], 0);
        tc_gemm<1><<<dim3(N_/BN, N_/BM, 4), 256, SMEM_BYTES, s2>>>(
            cc + (size_t)4 * c * N_ * N_, vc + (size_t)4 * c * N_ * N_,
            N_, (size_t)N_ * N_, x, x1h, nullptr, 4 * c, 0);
    }
    cudaEventRecord(evC, s2);

    // FFN pipeline: 4 GEMM halves strictly serial on main; LNs on s2.
    cudaStreamWaitEvent(0, evC, 0);
    cudaStreamWaitEvent(0, evWf, 0);
    const int HROWS = M_ / 2;              // 8192 rows
    const int HBLK  = HROWS / BM;          // 64 block rows

    // FFN1 halves (serial on main)
    for (int c = 0; c < 2; c++) {
        tc_gemm<2><<<dim3(D_/BN, HBLK, 1), 256, SMEM_BYTES>>>(
            x1h, wfT, D_, 0, nullptr, th, bf, 0, c * HBLK);
        cudaEventRecord(evF1[c], 0);
        // ln0 half c on s2 (overlaps next GEMM on main)
        cudaStreamWaitEvent(s2, evF1[c], 0);
        ln_swish_kernel<0><<<HROWS/8, 256, 0, s2>>>(lnf_s, lnf_b, nullptr, c * HROWS);
        cudaEventRecord(evL0[c], s2);
    }
    // FFN2 halves (serial on main, each waits only its ln0 half)
    for (int c = 0; c < 2; c++) {
        cudaStreamWaitEvent(0, evL0[c], 0);
        tc_gemm<2><<<dim3(D_/BN, HBLK, 1), 256, SMEM_BYTES>>>(
            zh, wfT + (size_t)D_*D_, D_, 0, nullptr, th, bf + D_, 0, c * HBLK);
        cudaEventRecord(evF2[c], 0);
        // ln1 half c on s2 (first overlaps second FFN2 half)
        cudaStreamWaitEvent(s2, evF2[c], 0);
        ln_swish_kernel<1><<<HROWS/8, 256, 0, s2>>>(lnf_s + D_, lnf_b + D_, out, c * HROWS);
    }
    cudaEventRecord(evDone, s2);
    cudaStreamWaitEvent(0, evDone, 0);
}

// round 16
// speedup vs baseline: 1.0307x; 1.0307x over previous
#include <cuda_runtime.h>
#include <cuda_fp16.h>
#include <cstdint>

// ---------------------------------------------------------------------------
// Problem shape
// ---------------------------------------------------------------------------
#define B_  16
#define N_  1024
#define D_  768
#define H_  12
#define HS_ 64
#define M_  (B_*N_)     // 16384 token rows
#define L_  2
#define EPS_ 1e-6f

// ---------------------------------------------------------------------------
// Scratch
// ---------------------------------------------------------------------------
__device__ __half g_xn [M_*D_];        // LN1(x)           (GEMM1 A)
__device__ __half g_wvT[D_*D_];        // Wv^T [n=h*64+k][d]
__device__ __half g_wfT[L_*D_*D_];     // Wf^T [l][n][d]
__device__ __half g_vc [H_*N_*N_];     // v [h][b*64+k][j] (circ B)
__device__ __half g_cc [H_*N_*N_];     // C [h][i][j]      (circ A)
__device__ __half g_x1h[M_*D_];        // x + y residual (fp16 only)
__device__ __half g_th [M_*D_];        // ffn gemm out (fp16)
__device__ __half g_zh [M_*D_];        // swish(ln(t))     (FFN2 A)

// ---------------------------------------------------------------------------
// Helpers
// ---------------------------------------------------------------------------
__device__ __forceinline__ uint32_t smem_u32(const void* p) {
    uint32_t a;
    asm("{ .reg .u64 t; cvta.to.shared.u64 t, %1; cvt.u32.u64 %0, t; }"
        : "=r"(a) : "l"(p));
    return a;
}
__device__ __forceinline__ void ldsm_x4(uint32_t* d, uint32_t addr) {
    asm volatile("ldmatrix.sync.aligned.m8n8.x4.shared.b16 {%0,%1,%2,%3}, [%4];"
                 : "=r"(d[0]), "=r"(d[1]), "=r"(d[2]), "=r"(d[3]) : "r"(addr));
}
__device__ __forceinline__ void mma16816(float* d, const uint32_t* a,
                                         uint32_t b0, uint32_t b1) {
    asm volatile(
        "mma.sync.aligned.m16n8k16.row.col.f32.f16.f16.f32 "
        "{%0,%1,%2,%3}, {%4,%5,%6,%7}, {%8,%9}, {%0,%1,%2,%3};"
        : "+f"(d[0]), "+f"(d[1]), "+f"(d[2]), "+f"(d[3])
        : "r"(a[0]), "r"(a[1]), "r"(a[2]), "r"(a[3]), "r"(b0), "r"(b1));
}
#define CP_ASYNC(dst, src) \
    asm volatile("cp.async.cg.shared.global [%0], [%1], 16;" :: "r"(dst), "l"(src))
#define CP_COMMIT() asm volatile("cp.async.commit_group;" ::: "memory")
#define CP_WAIT(n)  asm volatile("cp.async.wait_group %0;" :: "n"(n) : "memory")

// ---------------------------------------------------------------------------
// Weight prep: tiled transposes (both sides coalesced)
// ---------------------------------------------------------------------------
__global__ void __launch_bounds__(256) conv_wvT_kernel(const float* __restrict__ Wv) {
    __shared__ float ts[32][33];
    int d0 = blockIdx.x * 32, k0 = blockIdx.y * 32, h = blockIdx.z;
    int tx = threadIdx.x & 31, ty = threadIdx.x >> 5;
    #pragma unroll
    for (int r = 0; r < 4; r++) {
        int d = d0 + ty + r * 8;
        ts[ty + r * 8][tx] = Wv[((size_t)h * D_ + d) * HS_ + k0 + tx];
    }
    __syncthreads();
    #pragma unroll
    for (int r = 0; r < 4; r++) {
        int k = k0 + ty + r * 8;
        g_wvT[(size_t)(h * HS_ + k) * D_ + d0 + tx] = __float2half(ts[tx][ty + r * 8]);
    }
}
__global__ void __launch_bounds__(256) conv_wfT_kernel(const float* __restrict__ Wf) {
    __shared__ float ts[32][33];
    int d0 = blockIdx.x * 32, n0 = blockIdx.y * 32, l = blockIdx.z;
    int tx = threadIdx.x & 31, ty = threadIdx.x >> 5;
    #pragma unroll
    for (int r = 0; r < 4; r++) {
        int d = d0 + ty + r * 8;
        ts[ty + r * 8][tx] = Wf[((size_t)l * D_ + d) * D_ + n0 + tx];
    }
    __syncthreads();
    #pragma unroll
    for (int r = 0; r < 4; r++) {
        int n = n0 + ty + r * 8;
        g_wfT[((size_t)l * D_ + n) * D_ + d0 + tx] = __float2half(ts[tx][ty + r * 8]);
    }
}
__global__ void build_circ_kernel(const float* __restrict__ alpha) {
    int bid = blockIdx.x;           // h*1024 + i
    int h = bid >> 10, i = bid & 1023;
    const float* a = alpha + (size_t)h * N_;
    size_t base = (size_t)bid * N_;
    #pragma unroll
    for (int t = 0; t < 4; t++) {
        int j = threadIdx.x + t * 256;
        g_cc[base + j] = __float2half(a[(i - j) & (N_ - 1)]);
    }
}

// ---------------------------------------------------------------------------
// Warp-per-row LayerNorm (no smem, shuffle reduction). 8 rows/block.
// ---------------------------------------------------------------------------
__device__ __forceinline__ void warp_stats(const float4* v, float& mu, float& inv) {
    float s = 0.f, q = 0.f;
    #pragma unroll
    for (int i = 0; i < 6; i++) {
        s += v[i].x + v[i].y + v[i].z + v[i].w;
        q += v[i].x*v[i].x + v[i].y*v[i].y + v[i].z*v[i].z + v[i].w*v[i].w;
    }
    #pragma unroll
    for (int o = 16; o; o >>= 1) {
        s += __shfl_xor_sync(0xffffffffu, s, o);
        q += __shfl_xor_sync(0xffffffffu, q, o);
    }
    mu = s * (1.f / D_);
    float var = q * (1.f / D_) - mu * mu;
    inv = rsqrtf(var + EPS_);
}

__global__ void __launch_bounds__(256) ln1_kernel(
    const float* __restrict__ in, const float* __restrict__ scale,
    const float* __restrict__ bias)
{
    int warp = threadIdx.x >> 5, lane = threadIdx.x & 31;
    size_t row = (size_t)blockIdx.x * 8 + warp;
    const float4* p = reinterpret_cast<const float4*>(in + row * D_);
    const float4* sc = reinterpret_cast<const float4*>(scale);
    const float4* bi = reinterpret_cast<const float4*>(bias);
    float4 v[6];
    #pragma unroll
    for (int i = 0; i < 6; i++) v[i] = p[lane + 32 * i];
    float mu, inv;
    warp_stats(v, mu, inv);
    #pragma unroll
    for (int i = 0; i < 6; i++) {
        int g4 = lane + 32 * i;
        float4 s4 = sc[g4], b4 = bi[g4];
        __half2 h0 = __floats2half2_rn((v[i].x - mu) * inv * s4.x + b4.x,
                                       (v[i].y - mu) * inv * s4.y + b4.y);
        __half2 h1 = __floats2half2_rn((v[i].z - mu) * inv * s4.z + b4.z,
                                       (v[i].w - mu) * inv * s4.w + b4.w);
        uint2 u; u.x = *(uint32_t*)&h0; u.y = *(uint32_t*)&h1;
        *reinterpret_cast<uint2*>(g_xn + row * D_ + g4 * 4) = u;
    }
}

// input t is fp16. LAST=0: z = swish(LN(t)) -> g_zh
//                  LAST=1: out = log_cosh(swish(LN(t)) + x1h)
template<int LAST>
__global__ void __launch_bounds__(256) ln_swish_kernel(
    const float* __restrict__ scale, const float* __restrict__ bias,
    float* __restrict__ out)
{
    int warp = threadIdx.x >> 5, lane = threadIdx.x & 31;
    size_t row = (size_t)blockIdx.x * 8 + warp;
    const uint2* p = reinterpret_cast<const uint2*>(g_th + row * D_);
    const float4* sc = reinterpret_cast<const float4*>(scale);
    const float4* bi = reinterpret_cast<const float4*>(bias);
    float4 v[6];
    #pragma unroll
    for (int i = 0; i < 6; i++) {
        uint2 u = p[lane + 32 * i];
        __half2 h0 = *(__half2*)&u.x, h1 = *(__half2*)&u.y;
        float2 f0 = __half22float2(h0), f1 = __half22float2(h1);
        v[i] = make_float4(f0.x, f0.y, f1.x, f1.y);
    }
    float mu, inv;
    warp_stats(v, mu, inv);
    #pragma unroll
    for (int i = 0; i < 6; i++) {
        int g4 = lane + 32 * i;
        float4 s4 = sc[g4], b4 = bi[g4];
        float r[4] = {(v[i].x - mu) * inv * s4.x + b4.x,
                      (v[i].y - mu) * inv * s4.y + b4.y,
                      (v[i].z - mu) * inv * s4.z + b4.z,
                      (v[i].w - mu) * inv * s4.w + b4.w};
        #pragma unroll
        for (int c = 0; c < 4; c++) r[c] = r[c] * (1.f / (1.f + expf(-r[c])));
        if (LAST) {
            uint2 ux = *reinterpret_cast<const uint2*>(g_x1h + row * D_ + g4 * 4);
            float2 xa = __half22float2(*(__half2*)&ux.x);
            float2 xb = __half22float2(*(__half2*)&ux.y);
            float xs[4] = {xa.x, xa.y, xb.x, xb.y};
            float4 o4;
            float* po = &o4.x;
            #pragma unroll
            for (int c = 0; c < 4; c++) {
                float sum = r[c] + xs[c];
                float ax = fabsf(sum);
                po[c] = ax + log1pf(expf(-2.f * ax)) - 0.69314718055994530942f;
            }
            *reinterpret_cast<float4*>(out + row * D_ + g4 * 4) = o4;
        } else {
            __half2 h0 = __floats2half2_rn(r[0], r[1]);
            __half2 h1 = __floats2half2_rn(r[2], r[3]);
            uint2 u; u.x = *(uint32_t*)&h0; u.y = *(uint32_t*)&h1;
            *reinterpret_cast<uint2*>(g_zh + row * D_ + g4 * 4) = u;
        }
    }
}

// ---------------------------------------------------------------------------
// HMMA fp16 GEMM (fp32 accum). Block 128x128, BK=32, 3-stage cp.async,
// 2 CTAs/SM. 8 warps (2m x 4n), warp tile 64x32, m16n8k16.
// MODE 0: GEMM1 -> smem transpose, scatter v [h][b*64+k][j]; tileOff = col-tile
// MODE 1: circ  -> x1h = fp16(x + D); tileOff = head offset; strZ per head
// MODE 2: FFN   -> t = D + bias (fp16)
// ---------------------------------------------------------------------------
#define BM 128
#define BN 128
#define TILE_B   8192u            // 128x32 fp16
#define STAGE_B  (2u*TILE_B)      // A, B
#define NSTAGE   3
#define SMEM_BYTES (NSTAGE*STAGE_B)   // 49152 ; epi buffer 33280 fits

// 64B-row swizzle: 4 chunks of 16B; chunk' = cc ^ ((row>>1)&3)
__device__ __forceinline__ uint32_t sw_off(int row, int cc) {
    return (uint32_t)(row * 64 + ((cc ^ ((row >> 1) & 3)) << 4));
}

__device__ __forceinline__ void cp_tile(uint32_t dstBase, const __half* src,
                                        int rowBase, int kBase, int ld, int tid)
{
    const char* g = (const char*)src + ((size_t)rowBase * ld + kBase) * 2;
    #pragma unroll
    for (int t = 0; t < 2; t++) {
        int ci = tid + t * 256;
        int row = ci >> 2, cc = ci & 3;
        CP_ASYNC(dstBase + sw_off(row, cc), g + (size_t)row * ld * 2 + cc * 16);
    }
}

template<int MODE>
__global__ void __launch_bounds__(256, 2) tc_gemm(
    const __half* __restrict__ A, const __half* __restrict__ Bm,
    int Kdim, size_t strZ,
    const float* __restrict__ xin,            // mode1
    __half* __restrict__ out_h,               // mode0: vc, mode1: x1h, mode2: t
    const float* __restrict__ bias,           // mode2
    int tileOff)                              // mode0: col-tile, mode1: head
{
    extern __shared__ char smem[];
    const int tid = threadIdx.x;
    const int wid = tid >> 5, lane = tid & 31;
    const uint32_t sbase = smem_u32(smem);

    const int mBase = blockIdx.y * BM;
    const int nBase = (blockIdx.x + (MODE == 0 ? tileOff : 0)) * BN;
    const int bz = blockIdx.z;
    const __half* Ab = A  + (size_t)bz * strZ;
    const __half* Bb = Bm + (size_t)bz * strZ;

    const int warpM = wid >> 2;     // 0..1 (x64 rows)
    const int warpN = wid & 3;      // 0..3 (x32 cols)

    const int nc = Kdim >> 5;       // BK = 32

    #pragma unroll
    for (int s = 0; s < NSTAGE - 1; s++) {
        uint32_t sb = sbase + s * STAGE_B;
        cp_tile(sb,          Ab, mBase, s * 32, Kdim, tid);
        cp_tile(sb + TILE_B, Bb, nBase, s * 32, Kdim, tid);
        CP_COMMIT();
    }

    float acc[4][4][4] = {};
    const int lrow = lane & 15;
    const int lsel = lane >> 4;

    for (int c = 0; c < nc; c++) {
        CP_WAIT(NSTAGE - 2);
        __syncthreads();

        int pre = c + NSTAGE - 1;
        if (pre < nc) {
            uint32_t sb = sbase + (pre % NSTAGE) * STAGE_B;
            cp_tile(sb,          Ab, mBase, pre * 32, Kdim, tid);
            cp_tile(sb + TILE_B, Bb, nBase, pre * 32, Kdim, tid);
            CP_COMMIT();
        }

        uint32_t stA = sbase + (c % NSTAGE) * STAGE_B;
        uint32_t stB = stA + TILE_B;

        #pragma unroll
        for (int kk = 0; kk < 2; kk++) {
            int cc = kk * 2 + lsel;
            uint32_t aF[4][4], bF[2][4];
            #pragma unroll
            for (int mt = 0; mt < 4; mt++) {
                int r = warpM * 64 + mt * 16 + lrow;
                ldsm_x4(aF[mt], stA + sw_off(r, cc));
            }
            #pragma unroll
            for (int nt2 = 0; nt2 < 2; nt2++) {
                int r = warpN * 32 + nt2 * 16 + lrow;
                ldsm_x4(bF[nt2], stB + sw_off(r, cc));
            }
            #pragma unroll
            for (int mt = 0; mt < 4; mt++)
                #pragma unroll
                for (int nt = 0; nt < 4; nt++) {
                    uint32_t b0 = bF[nt >> 1][nt & 1];
                    uint32_t b1 = bF[nt >> 1][(nt & 1) + 2];
                    mma16816(acc[mt][nt], aF[mt], b0, b1);
                }
        }
    }
    CP_WAIT(0);

    const int mBaseW = mBase + warpM * 64;
    const int nBaseW = nBase + warpN * 32;

    if (MODE == 0) {
        // two 64-col chunks through smem [128][65], then column writes
        float* sbuf = reinterpret_cast<float*>(smem);
        const int LDS = 65;
        #pragma unroll
        for (int hf = 0; hf < 2; hf++) {
            __syncthreads();
            if ((warpN >> 1) == hf) {
                #pragma unroll
                for (int mt = 0; mt < 4; mt++)
                    #pragma unroll
                    for (int nt = 0; nt < 4; nt++) {
                        int rl = warpM * 64 + mt * 16 + (lane >> 2);
                        int cl = (warpN & 1) * 32 + nt * 8 + ((lane & 3) << 1);
                        sbuf[rl * LDS + cl]           = acc[mt][nt][0];
                        sbuf[rl * LDS + cl + 1]       = acc[mt][nt][1];
                        sbuf[(rl + 8) * LDS + cl]     = acc[mt][nt][2];
                        sbuf[(rl + 8) * LDS + cl + 1] = acc[mt][nt][3];
                    }
            }
            __syncthreads();
            #pragma unroll
            for (int i = 0; i < 8; i++) {
                int cl = wid * 8 + i;
                int cg = nBase + hf * 64 + cl;
                int h = cg >> 6, k = cg & 63;
                #pragma unroll
                for (int q = 0; q < 2; q++) {
                    int m = q * 64 + lane * 2;
                    int mg = mBase + m;
                    int b = mg >> 10, j = mg & 1023;
                    size_t o = (((size_t)(h << 10) + (b << 6) + k) << 10) + j;
                    __half2 hv = __floats2half2_rn(sbuf[m * LDS + cl],
                                                   sbuf[(m + 1) * LDS + cl]);
                    *reinterpret_cast<__half2*>(out_h + o) = hv;
                }
            }
        }
    } else {
        #pragma unroll
        for (int mt = 0; mt < 4; mt++)
            #pragma unroll
            for (int nt = 0; nt < 4; nt++) {
                int i0 = mBaseW + mt * 16 + (lane >> 2);
                int cl = nBaseW + nt * 8 + ((lane & 3) << 1);
                #pragma unroll
                for (int h2 = 0; h2 < 2; h2++) {
                    int i = i0 + h2 * 8;
                    float v0 = acc[mt][nt][h2 * 2];
                    float v1 = acc[mt][nt][h2 * 2 + 1];
                    if (MODE == 1) {
                        int b = cl >> 6, k = cl & 63;
                        size_t o = ((size_t)(b << 10) + i) * D_
                                   + (tileOff + bz) * HS_ + k;
                        *reinterpret_cast<__half2*>(out_h + o) =
                            __floats2half2_rn(xin[o] + v0, xin[o + 1] + v1);
                    } else {
                        size_t o = (size_t)i * D_ + cl;
                        *reinterpret_cast<__half2*>(out_h + o) =
                            __floats2half2_rn(v0 + bias[cl], v1 + bias[cl + 1]);
                    }
                }
            }
    }
}

// ---------------------------------------------------------------------------
// Launch: s2 = circ prep + chunked circ (pipelined behind GEMM1 column
// chunks); s3 = Wf prep. FFN chain serial on main stream.
// ---------------------------------------------------------------------------
extern "C" void kernel_launch(void* const* d_in, const int* in_sizes, int n_in,
                              void* d_out, int out_size)
{
    const float* x     = (const float*)d_in[0];
    const float* ln1_s = (const float*)d_in[1];
    const float* ln1_b = (const float*)d_in[2];
    const float* Wv    = (const float*)d_in[3];
    const float* alpha = (const float*)d_in[4];
    const float* Wf    = (const float*)d_in[5];
    const float* bf    = (const float*)d_in[6];
    const float* lnf_s = (const float*)d_in[7];
    const float* lnf_b = (const float*)d_in[8];
    float* out = (float*)d_out;

    static cudaStream_t s2 = nullptr, s3 = nullptr;
    static cudaEvent_t ev0, evWv, evWf, evC, evG[3];
    if (!s2) {
        cudaStreamCreateWithFlags(&s2, cudaStreamNonBlocking);
        cudaStreamCreateWithFlags(&s3, cudaStreamNonBlocking);
        cudaEventCreateWithFlags(&ev0,  cudaEventDisableTiming);
        cudaEventCreateWithFlags(&evWv, cudaEventDisableTiming);
        cudaEventCreateWithFlags(&evWf, cudaEventDisableTiming);
        cudaEventCreateWithFlags(&evC,  cudaEventDisableTiming);
        for (int i = 0; i < 3; i++)
            cudaEventCreateWithFlags(&evG[i], cudaEventDisableTiming);
        cudaFuncSetAttribute(tc_gemm<0>, cudaFuncAttributeMaxDynamicSharedMemorySize, SMEM_BYTES);
        cudaFuncSetAttribute(tc_gemm<1>, cudaFuncAttributeMaxDynamicSharedMemorySize, SMEM_BYTES);
        cudaFuncSetAttribute(tc_gemm<2>, cudaFuncAttributeMaxDynamicSharedMemorySize, SMEM_BYTES);
    }

    __half *xn, *wvT, *wfT, *vc, *cc, *x1h, *th, *zh;
    cudaGetSymbolAddress((void**)&xn, g_xn);
    cudaGetSymbolAddress((void**)&wvT, g_wvT);
    cudaGetSymbolAddress((void**)&wfT, g_wfT);
    cudaGetSymbolAddress((void**)&vc, g_vc);
    cudaGetSymbolAddress((void**)&cc, g_cc);
    cudaGetSymbolAddress((void**)&x1h, g_x1h);
    cudaGetSymbolAddress((void**)&th, g_th);
    cudaGetSymbolAddress((void**)&zh, g_zh);

    // fork prep
    cudaEventRecord(ev0, 0);
    cudaStreamWaitEvent(s2, ev0, 0);
    cudaStreamWaitEvent(s3, ev0, 0);
    conv_wvT_kernel<<<dim3(D_/32, HS_/32, H_), 256, 0, s2>>>(Wv);
    cudaEventRecord(evWv, s2);
    build_circ_kernel<<<H_*N_, 256, 0, s2>>>(alpha);
    conv_wfT_kernel<<<dim3(D_/32, D_/32, L_), 256, 0, s3>>>(Wf);
    cudaEventRecord(evWf, s3);

    // main: LN1
    ln1_kernel<<<M_/8, 256>>>(x, ln1_s, ln1_b);
    cudaStreamWaitEvent(0, evWv, 0);

    // GEMM1 column chunks (4 heads each) pipelined with circ chunks on s2
    for (int c = 0; c < 3; c++) {
        tc_gemm<0><<<dim3(2, M_/BM, 1), 256, SMEM_BYTES>>>(
            xn, wvT, D_, 0, nullptr, vc, nullptr, 2 * c);
        cudaEventRecord(evG[c], 0);
        cudaStreamWaitEvent(s2, evG[c], 0);
        tc_gemm<1><<<dim3(N_/BN, N_/BM, 4), 256, SMEM_BYTES, s2>>>(
            cc + (size_t)4 * c * N_ * N_, vc + (size_t)4 * c * N_ * N_,
            N_, (size_t)N_ * N_, x, x1h, nullptr, 4 * c);
    }
    cudaEventRecord(evC, s2);

    // FFN (waits on circ + Wf prep)
    cudaStreamWaitEvent(0, evC, 0);
    cudaStreamWaitEvent(0, evWf, 0);
    tc_gemm<2><<<dim3(D_/BN, M_/BM, 1), 256, SMEM_BYTES>>>(
        x1h, wfT, D_, 0, nullptr, th, bf, 0);
    ln_swish_kernel<0><<<M_/8, 256>>>(lnf_s, lnf_b, nullptr);

    tc_gemm<2><<<dim3(D_/BN, M_/BM, 1), 256, SMEM_BYTES>>>(
        zh, wfT + (size_t)D_*D_, D_, 0, nullptr, th, bf + D_, 0);
    ln_swish_kernel<1><<<M_/8, 256>>>(lnf_s + D_, lnf_b + D_, out);
}